// round 9
// baseline (speedup 1.0000x reference)
#include <cuda_runtime.h>

#define H 512
#define W 512
#define CH 3
#define NB 16               // batches
#define NS 48               // 16 batches * 3 channels
#define SYS (H*W)
#define NTOT (NS*SYS)
#define RTOT (NS*H)         // 24576 rows
#define WCN (511*512)
#define WRN (512*511)
#define WPTOT (NB*SYS)      // padded row-weight elements
#define MAXIT 100
#define EPS_F 158.32966f    // (1e-6 * 16*3*512*512)^2
#define TPB 512
#define NGRP (TPB/128)      // 4 sweep groups per block
#define MAXMEM 16           // max member blocks per system

__device__ float g_r[NTOT];
__device__ float g_pbuf[2][NTOT];
__device__ float g_wrp[WPTOT];        // row weights, padded stride 512 (col 511 = 0)
// per-block partial dots: [slot][system][member]  (plain stores, no atomics)
__device__ float g_prr[3][NS][MAXMEM];
__device__ float g_ppap[3][NS][MAXMEM];
// global convergence machinery
__device__ float g_sysrr[MAXIT][NS];
__device__ unsigned int g_cnt[MAXIT];
__device__ volatile int g_verdict[MAXIT];   // 0=pending 1=continue 2=stop
// barriers
__device__ unsigned int g_bar_arrive;
__device__ volatile unsigned int g_bar_phase;
__device__ unsigned int g_sarr[NS*32];
__device__ volatile unsigned int g_sph[NS*32];

__device__ __forceinline__ float4 ld4(const float* p) { return *reinterpret_cast<const float4*>(p); }
__device__ __forceinline__ void st4(float* p, float4 v) { *reinterpret_cast<float4*>(p) = v; }

__device__ __forceinline__ float nan0(float v) {
    if (isnan(v)) return 0.0f;
    if (isinf(v)) return v > 0.f ? 3.402823466e38f : -3.402823466e38f;
    return v;
}

__device__ __forceinline__ void grid_barrier(int G, unsigned int &gen) {
    __syncthreads();
    if (threadIdx.x == 0) {
        __threadfence();
        unsigned int t = atomicAdd(&g_bar_arrive, 1u);
        if (t == (unsigned int)(G - 1)) {
            g_bar_arrive = 0;
            __threadfence();
            g_bar_phase = gen + 1u;
        } else {
            while (g_bar_phase == gen) { __nanosleep(64); }
        }
        gen++;
        __threadfence();
    }
    __syncthreads();
}

// Per-system barrier over this block's 1-2 systems. Arrive-all-then-wait.
__device__ __forceinline__ void sys_barrier(int sa, int ca, int sb, int cb, int ns,
                                            unsigned int &ga, unsigned int &gb)
{
    __syncthreads();
    if (threadIdx.x == 0) {
        __threadfence();
        unsigned int t = atomicAdd(&g_sarr[sa * 32], 1u);
        if (t == (unsigned int)(ca - 1)) { g_sarr[sa*32] = 0; __threadfence(); g_sph[sa*32] = ga + 1u; }
        if (ns == 2) {
            unsigned int u = atomicAdd(&g_sarr[sb * 32], 1u);
            if (u == (unsigned int)(cb - 1)) { g_sarr[sb*32] = 0; __threadfence(); g_sph[sb*32] = gb + 1u; }
        }
        while (g_sph[sa*32] == ga) __nanosleep(32);
        ga++;
        if (ns == 2) { while (g_sph[sb*32] == gb) __nanosleep(32); gb++; }
        __threadfence();
    }
    __syncthreads();
}

__device__ __forceinline__ float psum(const float* a, int n) {
    float t = 0.f;
    for (int m = 0; m < n; m++) t += a[m];
    return t;
}

// Register-rolling sweep over rows [i0,i1) of one system (as R8).
template<int PASS, bool COMBINE>
__device__ __forceinline__ void sweep_seg(
    const float* __restrict__ zsrc, const float* __restrict__ pb, float coef,
    const float* __restrict__ wcb, const float* __restrict__ wrb,
    float* __restrict__ o1, float* __restrict__ o2,
    int i0, int i1, int j0, int lane, float &acc)
{
    float4 zu = make_float4(0.f,0.f,0.f,0.f), zc, zd = make_float4(0.f,0.f,0.f,0.f);

    if (i0 > 0) {
        int e = (i0 - 1) * W + j0;
        zu = ld4(zsrc + e);
        if (COMBINE) {
            float4 q = ld4(pb + e);
            zu.x = fmaf(coef, q.x, zu.x); zu.y = fmaf(coef, q.y, zu.y);
            zu.z = fmaf(coef, q.z, zu.z); zu.w = fmaf(coef, q.w, zu.w);
        }
    }
    {
        int e = i0 * W + j0;
        zc = ld4(zsrc + e);
        if (COMBINE) {
            float4 q = ld4(pb + e);
            zc.x = fmaf(coef, q.x, zc.x); zc.y = fmaf(coef, q.y, zc.y);
            zc.z = fmaf(coef, q.z, zc.z); zc.w = fmaf(coef, q.w, zc.w);
        }
    }

    int gi = i0 * W + j0;
    for (int i = i0; i < i1; ++i, gi += W) {
        const bool dn = (i < H - 1);
        if (dn) {
            zd = ld4(zsrc + gi + W);
            if (COMBINE) {
                float4 q = ld4(pb + gi + W);
                zd.x = fmaf(coef, q.x, zd.x); zd.y = fmaf(coef, q.y, zd.y);
                zd.z = fmaf(coef, q.z, zd.z); zd.w = fmaf(coef, q.w, zd.w);
            }
        }

        float4 wv = ld4(wrb + gi);          // padded row weights, aligned
        float wl = __shfl_up_sync(0xffffffffu, wv.w, 1);
        float xl = __shfl_up_sync(0xffffffffu, zc.w, 1);
        float xr = __shfl_down_sync(0xffffffffu, zc.x, 1);
        if (lane == 0) {
            if (j0 > 0) {
                xl = zsrc[gi - 1];
                if (COMBINE) xl = fmaf(coef, pb[gi - 1], xl);
                wl = wrb[gi - 1];
            } else wl = 0.f;
        }
        if (lane == 31 && j0 + 4 < W) {
            xr = zsrc[gi + 4];
            if (COMBINE) xr = fmaf(coef, pb[gi + 4], xr);
        }

        float y0 = zc.x, y1 = zc.y, y2 = zc.z, y3 = zc.w;
        if (i > 0) {
            float4 wu = ld4(wcb + (i - 1) * W + j0);
            y0 += wu.x * (zc.x - zu.x); y1 += wu.y * (zc.y - zu.y);
            y2 += wu.z * (zc.z - zu.z); y3 += wu.w * (zc.w - zu.w);
        }
        if (dn) {
            float4 wd = ld4(wcb + i * W + j0);
            y0 += wd.x * (zc.x - zd.x); y1 += wd.y * (zc.y - zd.y);
            y2 += wd.z * (zc.z - zd.z); y3 += wd.w * (zc.w - zd.w);
        }
        y0 += wv.x * (zc.x - zc.y);
        y1 += wv.x * (zc.y - zc.x) + wv.y * (zc.y - zc.z);
        y2 += wv.y * (zc.z - zc.y) + wv.z * (zc.z - zc.w);
        y3 += wv.z * (zc.w - zc.z);
        y0 += wl * (zc.x - xl);
        y3 += wv.w * (zc.w - xr);

        if (PASS == 0) {
            float4 rn = make_float4(zc.x - y0, zc.y - y1, zc.z - y2, zc.w - y3);
            st4(o1 + gi, rn);
            st4(o2 + gi, zc);
            acc += rn.x * rn.x + rn.y * rn.y + rn.z * rn.z + rn.w * rn.w;
        } else if (PASS == 1) {
            st4(o1 + gi, zc);
            acc += zc.x * y0 + zc.y * y1 + zc.z * y2 + zc.w * y3;
        } else {
            float4 rv = ld4(o1 + gi);
            float4 xv = ld4(o2 + gi);
            rv.x -= coef * y0; rv.y -= coef * y1;
            rv.z -= coef * y2; rv.w -= coef * y3;
            xv.x = fmaf(coef, zc.x, xv.x); xv.y = fmaf(coef, zc.y, xv.y);
            xv.z = fmaf(coef, zc.z, xv.z); xv.w = fmaf(coef, zc.w, xv.w);
            st4(o1 + gi, rv);
            st4(o2 + gi, xv);
            acc += rv.x * rv.x + rv.y * rv.y + rv.z * rv.z + rv.w * rv.w;
        }
        zu = zc; zc = zd;
    }
}

// Block-level reduce; thread0 plain-stores the block's partials (no atomics).
__device__ __forceinline__ void reduce2_store(float a0, float a1, float* d0, float* d1)
{
    __shared__ float sm[2][TPB / 32];
    #pragma unroll
    for (int o = 16; o; o >>= 1) {
        a0 += __shfl_down_sync(0xffffffffu, a0, o);
        a1 += __shfl_down_sync(0xffffffffu, a1, o);
    }
    int wid = threadIdx.x >> 5, lid = threadIdx.x & 31;
    if (lid == 0) { sm[0][wid] = a0; sm[1][wid] = a1; }
    __syncthreads();
    if (threadIdx.x < 32) {
        a0 = (lid < TPB / 32) ? sm[0][lid] : 0.f;
        a1 = (lid < TPB / 32) ? sm[1][lid] : 0.f;
        #pragma unroll
        for (int o = 16; o; o >>= 1) {
            a0 += __shfl_down_sync(0xffffffffu, a0, o);
            a1 += __shfl_down_sync(0xffffffffu, a1, o);
        }
        if (lid == 0) { *d0 = a0; if (d1) *d1 = a1; }
    }
    __syncthreads();
}

// Iterate system-aligned segments of [q0,q1): calls f(s, i0, i1).
template<typename F>
__device__ __forceinline__ void for_segs(int q0, int q1, F f)
{
    int a = q0;
    while (a < q1) {
        int s = a >> 9;
        int send = q1 < ((s + 1) << 9) ? q1 : ((s + 1) << 9);
        f(s, a & 511, (a & 511) + (send - a));
        a = send;
    }
}

// Owner posts system rr for iteration k; 48th contributor writes the verdict.
__device__ __forceinline__ void post_sys(int k, int s, int cnt, int slot)
{
    float tot = 0.f;
    for (int m = 0; m < cnt; m++) tot += g_prr[slot][s][m];
    g_sysrr[k][s] = tot;
    __threadfence();
    unsigned int c = atomicAdd(&g_cnt[k], 1u);
    if (c == (unsigned int)(NS - 1)) {
        __threadfence();
        float gt = 0.f;
        volatile float* vr = (volatile float*)g_sysrr[k];
        for (int t = 0; t < NS; t++) gt += vr[t];
        g_verdict[k] = (gt < EPS_F) ? 2 : 1;
    }
}

extern "C" __global__ void __launch_bounds__(TPB, 3)
cg_persistent(const float* __restrict__ Bin, const float* __restrict__ wc,
              const float* __restrict__ wr, float* __restrict__ x, int G)
{
    unsigned int gen = g_bar_phase;   // global barrier gen (replay-safe)
    const int bi = blockIdx.x;
    const int r0 = (int)(((long long)bi * RTOT) / G);
    const int r1 = (int)(((long long)(bi + 1) * RTOT) / G);
    const int s0 = r0 >> 9;
    const int sL = (r1 - 1) >> 9;
    const int nsys = (sL > s0) ? 2 : 1;
    // membership: fb(s) = owner of row s*512; lb(s) = owner of row (s+1)*512-1
    const int fb0 = (int)((((long long)s0 * H + 1) * G - 1) / RTOT);
    const int lb0 = (int)((((long long)(s0 + 1) * H) * G - 1) / RTOT);
    const int cnt0 = lb0 - fb0 + 1;
    const int mi0 = bi - fb0;
    int cnt1 = 0, mi1 = 0;
    if (nsys == 2) {
        const int fb1 = (int)((((long long)sL * H + 1) * G - 1) / RTOT);
        const int lb1 = (int)((((long long)(sL + 1) * H) * G - 1) / RTOT);
        cnt1 = lb1 - fb1 + 1;
        mi1 = bi - fb1;     // spanning block owns the second system (mi1 == 0)
    }
    unsigned int sg0 = g_sph[s0 * 32];
    unsigned int sg1 = (nsys == 2) ? g_sph[sL * 32] : 0u;

    const int grp = threadIdx.x >> 7;
    const int j0 = (threadIdx.x & 127) << 2;
    const int lane = threadIdx.x & 31;
    const int q0 = r0 + (int)(((long long)(r1 - r0) * grp) / NGRP);
    const int q1 = r0 + (int)(((long long)(r1 - r0) * (grp + 1)) / NGRP);

    // ---- Phase Z: zero verdict machinery; repack row weights (padded, zero col 511)
    if (bi == 0) {
        for (int t = threadIdx.x; t < MAXIT; t += TPB) {
            g_cnt[t] = 0u;
            g_verdict[t] = 0;
        }
    }
    for (int t = bi * TPB + threadIdx.x; t < WPTOT; t += G * TPB) {
        int b = t >> 18;
        int rem = t & (SYS - 1);
        int i = rem >> 9, j = rem & 511;
        g_wrp[t] = (j < 511) ? wr[b * WRN + i * 511 + j] : 0.f;
    }
    grid_barrier(G, gen);   // one global barrier per launch

    // ---- Setup: x = B; r = B - A*B; rr0 partials -> slot 0
    {
        float a0 = 0.f, a1 = 0.f;
        for_segs(q0, q1, [&](int s, int i0, int i1) {
            int b = s / CH;
            float acc = 0.f;
            sweep_seg<0, false>(Bin + s * SYS, (const float*)0, 0.f,
                                wc + b * WCN, g_wrp + b * SYS,
                                g_r + s * SYS, x + s * SYS, i0, i1, j0, lane, acc);
            if (s == s0) a0 += acc; else a1 += acc;
        });
        reduce2_store(a0, a1, &g_prr[0][s0][mi0],
                      nsys == 2 ? &g_prr[0][sL][mi1] : (float*)0);
    }
    sys_barrier(s0, cnt0, sL, cnt1, nsys, sg0, sg1);

    for (int k = 0; k < MAXIT; ++k) {
        const int cur = k % 3, prv = (k + 2) % 3, nxt = (k + 1) % 3;
        float* __restrict__ pnew = g_pbuf[k & 1];
        const float* __restrict__ pold = g_pbuf[(k + 1) & 1];

        // ---- Pass 1 (speculative w.r.t. verdict): p = r + beta*pold; pAp partials
        {
            float a0 = 0.f, a1 = 0.f;
            for_segs(q0, q1, [&](int s, int i0, int i1) {
                int b = s / CH;
                float acc = 0.f;
                if (k == 0) {
                    sweep_seg<1, false>(g_r + s * SYS, (const float*)0, 0.f,
                                        wc + b * WCN, g_wrp + b * SYS,
                                        pnew + s * SYS, (float*)0, i0, i1, j0, lane, acc);
                } else {
                    int cS = (s == s0) ? cnt0 : cnt1;
                    float beta = nan0(psum(g_prr[cur][s], cS) / psum(g_prr[prv][s], cS));
                    sweep_seg<1, true>(g_r + s * SYS, pold + s * SYS, beta,
                                       wc + b * WCN, g_wrp + b * SYS,
                                       pnew + s * SYS, (float*)0, i0, i1, j0, lane, acc);
                }
                if (s == s0) a0 += acc; else a1 += acc;
            });
            reduce2_store(a0, a1, &g_ppap[cur][s0][mi0],
                          nsys == 2 ? &g_ppap[cur][sL][mi1] : (float*)0);
        }
        sys_barrier(s0, cnt0, sL, cnt1, nsys, sg0, sg1);

        // ---- Global verdict for iteration k-1 (hidden behind pass1)
        if (k > 0) {
            __shared__ int s_v;
            if (threadIdx.x == 0) {
                int v;
                while ((v = g_verdict[k - 1]) == 0) __nanosleep(64);
                s_v = v;
            }
            __syncthreads();
            if (s_v == 2) break;   // x already holds x_k; p_k computed (matches ref)
        }

        // ---- Pass 2: recompute Ap; r -= a*Ap; x += a*p; rr partials -> slot nxt
        {
            float a0 = 0.f, a1 = 0.f;
            for_segs(q0, q1, [&](int s, int i0, int i1) {
                int b = s / CH;
                int cS = (s == s0) ? cnt0 : cnt1;
                float alpha = nan0(psum(g_prr[cur][s], cS) / psum(g_ppap[cur][s], cS));
                float acc = 0.f;
                sweep_seg<2, false>(pnew + s * SYS, (const float*)0, alpha,
                                    wc + b * WCN, g_wrp + b * SYS,
                                    g_r + s * SYS, x + s * SYS, i0, i1, j0, lane, acc);
                if (s == s0) a0 += acc; else a1 += acc;
            });
            reduce2_store(a0, a1, &g_prr[nxt][s0][mi0],
                          nsys == 2 ? &g_prr[nxt][sL][mi1] : (float*)0);
        }
        sys_barrier(s0, cnt0, sL, cnt1, nsys, sg0, sg1);

        // ---- Owners post rr_{k+1}; 48th contributor writes verdict[k]
        if (threadIdx.x == 0) {
            if (mi0 == 0) post_sys(k, s0, cnt0, nxt);
            if (nsys == 2 && mi1 == 0) post_sys(k, sL, cnt1, nxt);
        }
    }
}

extern "C" void kernel_launch(void* const* d_in, const int* in_sizes, int n_in,
                              void* d_out, int out_size)
{
    static int G = 0;
    if (G == 0) {
        int dev = 0;
        cudaGetDevice(&dev);
        int sms = 0;
        cudaDeviceGetAttribute(&sms, cudaDevAttrMultiProcessorCount, dev);
        int occ = 0;
        cudaOccupancyMaxActiveBlocksPerMultiprocessor(&occ, cg_persistent, TPB, 0);
        if (occ < 1) occ = 1;
        G = sms * occ;
        if (G > RTOT) G = RTOT;
    }
    cg_persistent<<<G, TPB>>>((const float*)d_in[0], (const float*)d_in[1],
                              (const float*)d_in[2], (float*)d_out, G);
}

// round 10
// speedup vs baseline: 1.1003x; 1.1003x over previous
#include <cuda_runtime.h>

#define H 512
#define W 512
#define CH 3
#define NB 16               // batches
#define NS 48               // 16 batches * 3 channels
#define SYS (H*W)
#define NTOT (NS*SYS)
#define BROW (NB*H)         // 8192 batch-rows
#define WCN (511*512)
#define WRN (512*511)
#define WPTOT (NB*SYS)      // padded row-weight elements
#define MAXIT 100
#define EPS_F 158.32966f    // (1e-6 * 16*3*512*512)^2
#define TPB 384             // 3 groups of 128 threads (one per channel)

__device__ float g_r[NTOT];
__device__ float g_pbuf[2][NTOT];
__device__ float g_wrp[WPTOT];       // row weights, padded stride 512 (col 511 = 0)
__device__ float g_pAp[3][NS*8];
__device__ float g_rr[3][NS*8];
__device__ unsigned int g_bar_arrive;
__device__ volatile unsigned int g_bar_phase;

__device__ __forceinline__ float4 ld4(const float* p) { return *reinterpret_cast<const float4*>(p); }
__device__ __forceinline__ void st4(float* p, float4 v) { *reinterpret_cast<float4*>(p) = v; }

__device__ __forceinline__ float nan0(float v) {
    if (isnan(v)) return 0.0f;
    if (isinf(v)) return v > 0.f ? 3.402823466e38f : -3.402823466e38f;
    return v;
}

__device__ __forceinline__ void grid_barrier(int G, unsigned int &gen) {
    __syncthreads();
    if (threadIdx.x == 0) {
        __threadfence();
        unsigned int t = atomicAdd(&g_bar_arrive, 1u);
        if (t == (unsigned int)(G - 1)) {
            g_bar_arrive = 0;
            __threadfence();
            g_bar_phase = gen + 1u;
        } else {
            while (g_bar_phase == gen) { __nanosleep(64); }
        }
        gen++;
        __threadfence();
    }
    __syncthreads();
}

// Register-rolling sweep over rows [i0,i1) of one system (identical math to R8).
// PASS 0 (setup): o1 <- z - y (=r), o2 <- z (=x), acc += |r|^2
// PASS 1:         o1 <- z (=p),                   acc += z . y  (p.Ap)
// PASS 2:         o1 -= coef*y (r), o2 += coef*z (x), acc += |r|^2
template<int PASS, bool COMBINE>
__device__ __forceinline__ void sweep_seg(
    const float* __restrict__ zsrc, const float* __restrict__ pb, float coef,
    const float* __restrict__ wcb, const float* __restrict__ wrb,
    float* __restrict__ o1, float* __restrict__ o2,
    int i0, int i1, int j0, int lane, float &acc)
{
    float4 zu = make_float4(0.f,0.f,0.f,0.f), zc, zd = make_float4(0.f,0.f,0.f,0.f);

    if (i0 > 0) {
        int e = (i0 - 1) * W + j0;
        zu = ld4(zsrc + e);
        if (COMBINE) {
            float4 q = ld4(pb + e);
            zu.x = fmaf(coef, q.x, zu.x); zu.y = fmaf(coef, q.y, zu.y);
            zu.z = fmaf(coef, q.z, zu.z); zu.w = fmaf(coef, q.w, zu.w);
        }
    }
    {
        int e = i0 * W + j0;
        zc = ld4(zsrc + e);
        if (COMBINE) {
            float4 q = ld4(pb + e);
            zc.x = fmaf(coef, q.x, zc.x); zc.y = fmaf(coef, q.y, zc.y);
            zc.z = fmaf(coef, q.z, zc.z); zc.w = fmaf(coef, q.w, zc.w);
        }
    }

    int gi = i0 * W + j0;
    for (int i = i0; i < i1; ++i, gi += W) {
        const bool dn = (i < H - 1);
        if (dn) {
            zd = ld4(zsrc + gi + W);
            if (COMBINE) {
                float4 q = ld4(pb + gi + W);
                zd.x = fmaf(coef, q.x, zd.x); zd.y = fmaf(coef, q.y, zd.y);
                zd.z = fmaf(coef, q.z, zd.z); zd.w = fmaf(coef, q.w, zd.w);
            }
        }

        float4 wv = ld4(wrb + gi);          // padded row weights, aligned ld4
        float wl = __shfl_up_sync(0xffffffffu, wv.w, 1);
        float xl = __shfl_up_sync(0xffffffffu, zc.w, 1);
        float xr = __shfl_down_sync(0xffffffffu, zc.x, 1);
        if (lane == 0) {
            if (j0 > 0) {
                xl = zsrc[gi - 1];
                if (COMBINE) xl = fmaf(coef, pb[gi - 1], xl);
                wl = wrb[gi - 1];
            } else wl = 0.f;
        }
        if (lane == 31 && j0 + 4 < W) {
            xr = zsrc[gi + 4];
            if (COMBINE) xr = fmaf(coef, pb[gi + 4], xr);
        }

        float y0 = zc.x, y1 = zc.y, y2 = zc.z, y3 = zc.w;
        if (i > 0) {                         // up weights: re-load (L1 hit)
            float4 wu = ld4(wcb + (i - 1) * W + j0);
            y0 += wu.x * (zc.x - zu.x); y1 += wu.y * (zc.y - zu.y);
            y2 += wu.z * (zc.z - zu.z); y3 += wu.w * (zc.w - zu.w);
        }
        if (dn) {
            float4 wd = ld4(wcb + i * W + j0);
            y0 += wd.x * (zc.x - zd.x); y1 += wd.y * (zc.y - zd.y);
            y2 += wd.z * (zc.z - zd.z); y3 += wd.w * (zc.w - zd.w);
        }
        y0 += wv.x * (zc.x - zc.y);
        y1 += wv.x * (zc.y - zc.x) + wv.y * (zc.y - zc.z);
        y2 += wv.y * (zc.z - zc.y) + wv.z * (zc.z - zc.w);
        y3 += wv.z * (zc.w - zc.z);
        y0 += wl * (zc.x - xl);
        y3 += wv.w * (zc.w - xr);            // wv.w==0 at right edge (padded)

        if (PASS == 0) {
            float4 rn = make_float4(zc.x - y0, zc.y - y1, zc.z - y2, zc.w - y3);
            st4(o1 + gi, rn);
            st4(o2 + gi, zc);
            acc += rn.x * rn.x + rn.y * rn.y + rn.z * rn.z + rn.w * rn.w;
        } else if (PASS == 1) {
            st4(o1 + gi, zc);
            acc += zc.x * y0 + zc.y * y1 + zc.z * y2 + zc.w * y3;
        } else {
            float4 rv = ld4(o1 + gi);
            float4 xv = ld4(o2 + gi);
            rv.x -= coef * y0; rv.y -= coef * y1;
            rv.z -= coef * y2; rv.w -= coef * y3;
            xv.x = fmaf(coef, zc.x, xv.x); xv.y = fmaf(coef, zc.y, xv.y);
            xv.z = fmaf(coef, zc.z, xv.z); xv.w = fmaf(coef, zc.w, xv.w);
            st4(o1 + gi, rv);
            st4(o2 + gi, xv);
            acc += rv.x * rv.x + rv.y * rv.y + rv.z * rv.z + rv.w * rv.w;
        }
        zu = zc; zc = zd;
    }
}

// Per-group (128-thread) reduce; one atomicAdd per group per covered batch.
// dst0/dst1 are the scalar slots for (batch0, grp-channel) / (batch1, grp-channel).
__device__ __forceinline__ void reduce_grp_atomic(float a0, float a1, int grp,
                                                  float* dst0, float* dst1)
{
    __shared__ float sm[2][3][4];
    #pragma unroll
    for (int o = 16; o; o >>= 1) {
        a0 += __shfl_down_sync(0xffffffffu, a0, o);
        a1 += __shfl_down_sync(0xffffffffu, a1, o);
    }
    int wg = (threadIdx.x >> 5) & 3;     // warp within group
    int lane = threadIdx.x & 31;
    if (lane == 0) { sm[0][grp][wg] = a0; sm[1][grp][wg] = a1; }
    __syncthreads();
    if (wg == 0 && lane == 0) {
        float t0 = sm[0][grp][0] + sm[0][grp][1] + sm[0][grp][2] + sm[0][grp][3];
        atomicAdd(dst0, t0);
        if (dst1) {
            float t1 = sm[1][grp][0] + sm[1][grp][1] + sm[1][grp][2] + sm[1][grp][3];
            atomicAdd(dst1, t1);
        }
    }
    __syncthreads();
}

// Iterate batch-aligned segments of batch-row range [q0,q1): calls f(b, i0, i1).
template<typename F>
__device__ __forceinline__ void for_segs(int q0, int q1, F f)
{
    int a = q0;
    while (a < q1) {
        int b = a >> 9;
        int send = q1 < ((b + 1) << 9) ? q1 : ((b + 1) << 9);
        f(b, a & 511, (a & 511) + (send - a));
        a = send;
    }
}

extern "C" __global__ void __launch_bounds__(TPB, 4)
cg_persistent(const float* __restrict__ Bin, const float* __restrict__ wc,
              const float* __restrict__ wr, float* __restrict__ x, int G)
{
    unsigned int gen = g_bar_phase;   // survives graph replays
    const int bi = blockIdx.x;
    // block covers batch-rows [r0,r1); all 3 channel-groups sweep the same rows
    const int r0 = (int)(((long long)bi * BROW) / G);
    const int r1 = (int)(((long long)(bi + 1) * BROW) / G);
    const int b0 = r0 >> 9;           // first batch this block touches
    const int grp = threadIdx.x >> 7;           // channel 0..2
    const int j0 = (threadIdx.x & 127) << 2;
    const int lane = threadIdx.x & 31;
    const bool has2 = ((r1 - 1) >> 9) > b0;     // spans a second batch
    // scalar-slot indices for this group's channel
    const int sA = (b0 * CH + grp) * 8;
    const int sB = ((b0 + 1) * CH + grp) * 8;   // valid only if has2

    // Phase Z: zero scalar slots + build padded row-weight buffer
    if (bi == 0) {
        for (int t = threadIdx.x; t < 3 * NS * 8; t += TPB) {
            (&g_pAp[0][0])[t] = 0.f;
            (&g_rr[0][0])[t] = 0.f;
        }
    }
    for (int t = bi * TPB + threadIdx.x; t < WPTOT; t += G * TPB) {
        int b = t >> 18;
        int rem = t & (SYS - 1);
        int i = rem >> 9, j = rem & 511;
        g_wrp[t] = (j < 511) ? wr[b * WRN + i * 511 + j] : 0.f;
    }
    grid_barrier(G, gen);

    // Setup: x = B; r = B - A*B; rr0 -> slot 0
    {
        float a0 = 0.f, a1 = 0.f;
        for_segs(r0, r1, [&](int b, int i0, int i1) {
            int s = b * CH + grp;
            float acc = 0.f;
            sweep_seg<0, false>(Bin + s * SYS, (const float*)0, 0.f,
                                wc + b * WCN, g_wrp + b * SYS,
                                g_r + s * SYS, x + s * SYS, i0, i1, j0, lane, acc);
            if (b == b0) a0 += acc; else a1 += acc;
        });
        reduce_grp_atomic(a0, a1, grp, &g_rr[0][sA], has2 ? &g_rr[0][sB] : (float*)0);
    }
    grid_barrier(G, gen);

    for (int it = 0; it < MAXIT; ++it) {
        const int cur = it % 3, prv = (it + 2) % 3, nxt = (it + 1) % 3;
        float* __restrict__ pnew = g_pbuf[it & 1];
        const float* __restrict__ pold = g_pbuf[(it + 1) & 1];

        // Pass 1: p = r + beta*p_old formed on load; store p; pAp dot
        {
            float a0 = 0.f, a1 = 0.f;
            for_segs(r0, r1, [&](int b, int i0, int i1) {
                int s = b * CH + grp;
                float acc = 0.f;
                if (it == 0) {
                    sweep_seg<1, false>(g_r + s * SYS, (const float*)0, 0.f,
                                        wc + b * WCN, g_wrp + b * SYS,
                                        pnew + s * SYS, (float*)0, i0, i1, j0, lane, acc);
                } else {
                    float beta = nan0(g_rr[cur][s * 8] / g_rr[prv][s * 8]);
                    sweep_seg<1, true>(g_r + s * SYS, pold + s * SYS, beta,
                                       wc + b * WCN, g_wrp + b * SYS,
                                       pnew + s * SYS, (float*)0, i0, i1, j0, lane, acc);
                }
                if (b == b0) a0 += acc; else a1 += acc;
            });
            reduce_grp_atomic(a0, a1, grp, &g_pAp[cur][sA], has2 ? &g_pAp[cur][sB] : (float*)0);
            if (bi == 0) {
                for (int t = threadIdx.x; t < NS * 8; t += TPB) g_rr[nxt][t] = 0.f;
            }
        }
        grid_barrier(G, gen);

        // Pass 2: recompute Ap from p; r -= a*Ap; x += a*p; rr dot
        {
            float a0 = 0.f, a1 = 0.f;
            for_segs(r0, r1, [&](int b, int i0, int i1) {
                int s = b * CH + grp;
                float alpha = nan0(g_rr[cur][s * 8] / g_pAp[cur][s * 8]);
                float acc = 0.f;
                sweep_seg<2, false>(pnew + s * SYS, (const float*)0, alpha,
                                    wc + b * WCN, g_wrp + b * SYS,
                                    g_r + s * SYS, x + s * SYS, i0, i1, j0, lane, acc);
                if (b == b0) a0 += acc; else a1 += acc;
            });
            reduce_grp_atomic(a0, a1, grp, &g_rr[nxt][sA], has2 ? &g_rr[nxt][sB] : (float*)0);
            if (bi == 0) {
                for (int t = threadIdx.x; t < NS * 8; t += TPB) g_pAp[nxt][t] = 0.f;
            }
        }
        grid_barrier(G, gen);

        // Convergence (uniform across blocks)
        __shared__ int s_done;
        if (threadIdx.x == 0) {
            float tot = 0.f;
            for (int s = 0; s < NS; ++s) tot += g_rr[nxt][s * 8];
            s_done = (tot < EPS_F) ? 1 : 0;
        }
        __syncthreads();
        if (s_done) break;
    }
}

extern "C" void kernel_launch(void* const* d_in, const int* in_sizes, int n_in,
                              void* d_out, int out_size)
{
    static int G = 0;
    if (G == 0) {
        int dev = 0;
        cudaGetDevice(&dev);
        int sms = 0;
        cudaDeviceGetAttribute(&sms, cudaDevAttrMultiProcessorCount, dev);
        int occ = 0;
        cudaOccupancyMaxActiveBlocksPerMultiprocessor(&occ, cg_persistent, TPB, 0);
        if (occ < 1) occ = 1;
        G = sms * occ;
        if (G > BROW) G = BROW;
    }
    cg_persistent<<<G, TPB>>>((const float*)d_in[0], (const float*)d_in[1],
                              (const float*)d_in[2], (float*)d_out, G);
}

// round 11
// speedup vs baseline: 1.1262x; 1.0235x over previous
#include <cuda_runtime.h>

#define H 512
#define W 512
#define CH 3
#define NB 16               // batches
#define NS 48               // 16 batches * 3 channels
#define SYS (H*W)
#define NTOT (NS*SYS)
#define BROW (NB*H)         // 8192 batch-rows
#define WCN (511*512)
#define WRN (512*511)
#define WPTOT (NB*SYS)      // padded row-weight elements
#define MAXIT 100
#define EPS_F 158.32966f    // (1e-6 * 16*3*512*512)^2
#define TPB 384             // 3 groups of 128 threads (one per channel)

__device__ float g_r[NTOT];
__device__ float g_pbuf[2][NTOT];
__device__ float g_wrp[WPTOT];       // row weights, padded stride 512 (col 511 = 0)
__device__ float g_pAp[3][NS*8];
__device__ float g_rr[3][NS*8];
__device__ unsigned int g_bar_arrive;
__device__ volatile unsigned int g_bar_phase;

__device__ __forceinline__ float4 ld4(const float* p) { return *reinterpret_cast<const float4*>(p); }
__device__ __forceinline__ void st4(float* p, float4 v) { *reinterpret_cast<float4*>(p) = v; }

__device__ __forceinline__ float nan0(float v) {
    if (isnan(v)) return 0.0f;
    if (isinf(v)) return v > 0.f ? 3.402823466e38f : -3.402823466e38f;
    return v;
}

__device__ __forceinline__ void grid_barrier(int G, unsigned int &gen) {
    __syncthreads();
    if (threadIdx.x == 0) {
        __threadfence();
        unsigned int t = atomicAdd(&g_bar_arrive, 1u);
        if (t == (unsigned int)(G - 1)) {
            g_bar_arrive = 0;
            __threadfence();
            g_bar_phase = gen + 1u;
        } else {
            while (g_bar_phase == gen) { __nanosleep(64); }
        }
        gen++;
        __threadfence();
    }
    __syncthreads();
}

template<bool COMBINE>
__device__ __forceinline__ float4 ldz(const float* __restrict__ z,
                                      const float* __restrict__ pb,
                                      float coef, int e)
{
    float4 v = ld4(z + e);
    if (COMBINE) {
        float4 q = ld4(pb + e);
        v.x = fmaf(coef, q.x, v.x); v.y = fmaf(coef, q.y, v.y);
        v.z = fmaf(coef, q.z, v.z); v.w = fmaf(coef, q.w, v.w);
    }
    return v;
}

// One stencil row. Boundary handling is branchless: invalid-side weight
// vectors (wcu/wcd) and z rows are pre-zeroed by the caller.
template<int PASS, bool COMBINE>
__device__ __forceinline__ void do_row(
    float4 zu, float4 zc, float4 zd,
    float4 wcu, float4 wcd, float4 wv,
    const float* __restrict__ zsrc, const float* __restrict__ pb, float coef,
    const float* __restrict__ wrb,
    float* __restrict__ o1, float* __restrict__ o2,
    int gi, int lane, int j0, float &acc)
{
    float wl = __shfl_up_sync(0xffffffffu, wv.w, 1);
    float xl = __shfl_up_sync(0xffffffffu, zc.w, 1);
    float xr = __shfl_down_sync(0xffffffffu, zc.x, 1);
    if (lane == 0) {
        if (j0 > 0) {
            xl = zsrc[gi - 1];
            if (COMBINE) xl = fmaf(coef, pb[gi - 1], xl);
            wl = wrb[gi - 1];
        } else wl = 0.f;
    }
    if (lane == 31 && j0 + 4 < W) {
        xr = zsrc[gi + 4];
        if (COMBINE) xr = fmaf(coef, pb[gi + 4], xr);
    }

    float y0 = zc.x, y1 = zc.y, y2 = zc.z, y3 = zc.w;
    y0 += wcu.x * (zc.x - zu.x); y1 += wcu.y * (zc.y - zu.y);
    y2 += wcu.z * (zc.z - zu.z); y3 += wcu.w * (zc.w - zu.w);
    y0 += wcd.x * (zc.x - zd.x); y1 += wcd.y * (zc.y - zd.y);
    y2 += wcd.z * (zc.z - zd.z); y3 += wcd.w * (zc.w - zd.w);
    y0 += wv.x * (zc.x - zc.y);
    y1 += wv.x * (zc.y - zc.x) + wv.y * (zc.y - zc.z);
    y2 += wv.y * (zc.z - zc.y) + wv.z * (zc.z - zc.w);
    y3 += wv.z * (zc.w - zc.z);
    y0 += wl * (zc.x - xl);
    y3 += wv.w * (zc.w - xr);            // wv.w==0 at right edge (padded)

    if (PASS == 0) {
        float4 rn = make_float4(zc.x - y0, zc.y - y1, zc.z - y2, zc.w - y3);
        st4(o1 + gi, rn);
        st4(o2 + gi, zc);
        acc += rn.x * rn.x + rn.y * rn.y + rn.z * rn.z + rn.w * rn.w;
    } else if (PASS == 1) {
        st4(o1 + gi, zc);
        acc += zc.x * y0 + zc.y * y1 + zc.z * y2 + zc.w * y3;
    } else {
        float4 rv = ld4(o1 + gi);
        float4 xv = ld4(o2 + gi);
        rv.x -= coef * y0; rv.y -= coef * y1;
        rv.z -= coef * y2; rv.w -= coef * y3;
        xv.x = fmaf(coef, zc.x, xv.x); xv.y = fmaf(coef, zc.y, xv.y);
        xv.z = fmaf(coef, zc.z, xv.z); xv.w = fmaf(coef, zc.w, xv.w);
        st4(o1 + gi, rv);
        st4(o2 + gi, xv);
        acc += rv.x * rv.x + rv.y * rv.y + rv.z * rv.z + rv.w * rv.w;
    }
}

// Register-rolling sweep over rows [i0,i1), unrolled by 2 for MLP:
// each pair-iteration issues both z loads, both row-weight loads and all
// three column-weight loads before computing.
template<int PASS, bool COMBINE>
__device__ __forceinline__ void sweep_seg(
    const float* __restrict__ zsrc, const float* __restrict__ pb, float coef,
    const float* __restrict__ wcb, const float* __restrict__ wrb,
    float* __restrict__ o1, float* __restrict__ o2,
    int i0, int i1, int j0, int lane, float &acc)
{
    const float4 Z0 = make_float4(0.f, 0.f, 0.f, 0.f);
    float4 zu = Z0, zc, zd, ze;

    if (i0 > 0) zu = ldz<COMBINE>(zsrc, pb, coef, (i0 - 1) * W + j0);
    zc = ldz<COMBINE>(zsrc, pb, coef, i0 * W + j0);

    int i = i0;
    int gi = i0 * W + j0;
    for (; i + 2 <= i1; i += 2, gi += 2 * W) {
        const bool up  = (i > 0);
        const bool dn2 = (i + 2 < H);
        zd = ldz<COMBINE>(zsrc, pb, coef, gi + W);           // row i+1 (always exists)
        ze = dn2 ? ldz<COMBINE>(zsrc, pb, coef, gi + 2 * W) : Z0;
        float4 wv  = ld4(wrb + gi);
        float4 wv2 = ld4(wrb + gi + W);
        float4 wcu = up  ? ld4(wcb + (i - 1) * W + j0) : Z0;
        float4 wcm = ld4(wcb + i * W + j0);                  // i <= H-2 here
        float4 wcd = dn2 ? ld4(wcb + (i + 1) * W + j0) : Z0;

        do_row<PASS, COMBINE>(zu, zc, zd, wcu, wcm, wv,
                              zsrc, pb, coef, wrb, o1, o2, gi, lane, j0, acc);
        do_row<PASS, COMBINE>(zc, zd, ze, wcm, wcd, wv2,
                              zsrc, pb, coef, wrb, o1, o2, gi + W, lane, j0, acc);
        zu = zd; zc = ze;
    }
    if (i < i1) {                                            // peel (≤1 row)
        const bool up = (i > 0), dn = (i < H - 1);
        zd = dn ? ldz<COMBINE>(zsrc, pb, coef, gi + W) : Z0;
        float4 wv  = ld4(wrb + gi);
        float4 wcu = up ? ld4(wcb + (i - 1) * W + j0) : Z0;
        float4 wcd = dn ? ld4(wcb + i * W + j0) : Z0;
        do_row<PASS, COMBINE>(zu, zc, zd, wcu, wcd, wv,
                              zsrc, pb, coef, wrb, o1, o2, gi, lane, j0, acc);
    }
}

// Per-group (128-thread) reduce; one atomicAdd per group per covered batch.
__device__ __forceinline__ void reduce_grp_atomic(float a0, float a1, int grp,
                                                  float* dst0, float* dst1)
{
    __shared__ float sm[2][3][4];
    #pragma unroll
    for (int o = 16; o; o >>= 1) {
        a0 += __shfl_down_sync(0xffffffffu, a0, o);
        a1 += __shfl_down_sync(0xffffffffu, a1, o);
    }
    int wg = (threadIdx.x >> 5) & 3;     // warp within group
    int lane = threadIdx.x & 31;
    if (lane == 0) { sm[0][grp][wg] = a0; sm[1][grp][wg] = a1; }
    __syncthreads();
    if (wg == 0 && lane == 0) {
        float t0 = sm[0][grp][0] + sm[0][grp][1] + sm[0][grp][2] + sm[0][grp][3];
        atomicAdd(dst0, t0);
        if (dst1) {
            float t1 = sm[1][grp][0] + sm[1][grp][1] + sm[1][grp][2] + sm[1][grp][3];
            atomicAdd(dst1, t1);
        }
    }
    __syncthreads();
}

// Iterate batch-aligned segments of batch-row range [q0,q1): calls f(b, i0, i1).
template<typename F>
__device__ __forceinline__ void for_segs(int q0, int q1, F f)
{
    int a = q0;
    while (a < q1) {
        int b = a >> 9;
        int send = q1 < ((b + 1) << 9) ? q1 : ((b + 1) << 9);
        f(b, a & 511, (a & 511) + (send - a));
        a = send;
    }
}

extern "C" __global__ void __launch_bounds__(TPB, 3)
cg_persistent(const float* __restrict__ Bin, const float* __restrict__ wc,
              const float* __restrict__ wr, float* __restrict__ x, int G)
{
    unsigned int gen = g_bar_phase;   // survives graph replays
    const int bi = blockIdx.x;
    const int r0 = (int)(((long long)bi * BROW) / G);
    const int r1 = (int)(((long long)(bi + 1) * BROW) / G);
    const int b0 = r0 >> 9;
    const int grp = threadIdx.x >> 7;           // channel 0..2
    const int j0 = (threadIdx.x & 127) << 2;
    const int lane = threadIdx.x & 31;
    const bool has2 = ((r1 - 1) >> 9) > b0;
    const int sA = (b0 * CH + grp) * 8;
    const int sB = ((b0 + 1) * CH + grp) * 8;

    // Phase Z: zero scalar slots + build padded row-weight buffer
    if (bi == 0) {
        for (int t = threadIdx.x; t < 3 * NS * 8; t += TPB) {
            (&g_pAp[0][0])[t] = 0.f;
            (&g_rr[0][0])[t] = 0.f;
        }
    }
    for (int t = bi * TPB + threadIdx.x; t < WPTOT; t += G * TPB) {
        int b = t >> 18;
        int rem = t & (SYS - 1);
        int i = rem >> 9, j = rem & 511;
        g_wrp[t] = (j < 511) ? wr[b * WRN + i * 511 + j] : 0.f;
    }
    grid_barrier(G, gen);

    // Setup: x = B; r = B - A*B; rr0 -> slot 0
    {
        float a0 = 0.f, a1 = 0.f;
        for_segs(r0, r1, [&](int b, int i0, int i1) {
            int s = b * CH + grp;
            float acc = 0.f;
            sweep_seg<0, false>(Bin + s * SYS, (const float*)0, 0.f,
                                wc + b * WCN, g_wrp + b * SYS,
                                g_r + s * SYS, x + s * SYS, i0, i1, j0, lane, acc);
            if (b == b0) a0 += acc; else a1 += acc;
        });
        reduce_grp_atomic(a0, a1, grp, &g_rr[0][sA], has2 ? &g_rr[0][sB] : (float*)0);
    }
    grid_barrier(G, gen);

    for (int it = 0; it < MAXIT; ++it) {
        const int cur = it % 3, prv = (it + 2) % 3, nxt = (it + 1) % 3;
        float* __restrict__ pnew = g_pbuf[it & 1];
        const float* __restrict__ pold = g_pbuf[(it + 1) & 1];

        // Pass 1: p = r + beta*p_old formed on load; store p; pAp dot
        {
            float a0 = 0.f, a1 = 0.f;
            for_segs(r0, r1, [&](int b, int i0, int i1) {
                int s = b * CH + grp;
                float acc = 0.f;
                if (it == 0) {
                    sweep_seg<1, false>(g_r + s * SYS, (const float*)0, 0.f,
                                        wc + b * WCN, g_wrp + b * SYS,
                                        pnew + s * SYS, (float*)0, i0, i1, j0, lane, acc);
                } else {
                    float beta = nan0(g_rr[cur][s * 8] / g_rr[prv][s * 8]);
                    sweep_seg<1, true>(g_r + s * SYS, pold + s * SYS, beta,
                                       wc + b * WCN, g_wrp + b * SYS,
                                       pnew + s * SYS, (float*)0, i0, i1, j0, lane, acc);
                }
                if (b == b0) a0 += acc; else a1 += acc;
            });
            reduce_grp_atomic(a0, a1, grp, &g_pAp[cur][sA], has2 ? &g_pAp[cur][sB] : (float*)0);
            if (bi == 0) {
                for (int t = threadIdx.x; t < NS * 8; t += TPB) g_rr[nxt][t] = 0.f;
            }
        }
        grid_barrier(G, gen);

        // Pass 2: recompute Ap from p; r -= a*Ap; x += a*p; rr dot
        {
            float a0 = 0.f, a1 = 0.f;
            for_segs(r0, r1, [&](int b, int i0, int i1) {
                int s = b * CH + grp;
                float alpha = nan0(g_rr[cur][s * 8] / g_pAp[cur][s * 8]);
                float acc = 0.f;
                sweep_seg<2, false>(pnew + s * SYS, (const float*)0, alpha,
                                    wc + b * WCN, g_wrp + b * SYS,
                                    g_r + s * SYS, x + s * SYS, i0, i1, j0, lane, acc);
                if (b == b0) a0 += acc; else a1 += acc;
            });
            reduce_grp_atomic(a0, a1, grp, &g_rr[nxt][sA], has2 ? &g_rr[nxt][sB] : (float*)0);
            if (bi == 0) {
                for (int t = threadIdx.x; t < NS * 8; t += TPB) g_pAp[nxt][t] = 0.f;
            }
        }
        grid_barrier(G, gen);

        // Convergence (uniform across blocks)
        __shared__ int s_done;
        if (threadIdx.x == 0) {
            float tot = 0.f;
            for (int s = 0; s < NS; ++s) tot += g_rr[nxt][s * 8];
            s_done = (tot < EPS_F) ? 1 : 0;
        }
        __syncthreads();
        if (s_done) break;
    }
}

extern "C" void kernel_launch(void* const* d_in, const int* in_sizes, int n_in,
                              void* d_out, int out_size)
{
    static int G = 0;
    if (G == 0) {
        int dev = 0;
        cudaGetDevice(&dev);
        int sms = 0;
        cudaDeviceGetAttribute(&sms, cudaDevAttrMultiProcessorCount, dev);
        int occ = 0;
        cudaOccupancyMaxActiveBlocksPerMultiprocessor(&occ, cg_persistent, TPB, 0);
        if (occ < 1) occ = 1;
        G = sms * occ;
        if (G > BROW) G = BROW;
    }
    cg_persistent<<<G, TPB>>>((const float*)d_in[0], (const float*)d_in[1],
                              (const float*)d_in[2], (float*)d_out, G);
}